// round 6
// baseline (speedup 1.0000x reference)
#include <cuda_runtime.h>
#include <math.h>

#define B   64
#define T   1000
#define RNN 1024
#define EMB 512
#define ATT 128
#define LOC 32
#define KS  31
#define ECH 20
#define ETILE 50
#define EB  10
#define TCH 25
#define CTILE 40

__device__ float g_pq[B * ATT];
__device__ float g_energy[B * T];
__device__ float2 g_ms[B * ECH];
__device__ float g_partial[B * TCH * EMB];
__device__ int   g_cnt[B];

__device__ __forceinline__ float fast_tanh(float x) {
    float y;
    asm("tanh.approx.f32 %0, %1;" : "=f"(y) : "f"(x));
    return y;
}
__device__ __forceinline__ unsigned long long fma2(unsigned long long a,
                                                   unsigned long long b,
                                                   unsigned long long c) {
    unsigned long long d;
    asm("fma.rn.f32x2 %0, %1, %2, %3;" : "=l"(d) : "l"(a), "l"(b), "l"(c));
    return d;
}
__device__ __forceinline__ unsigned long long pack2(float lo, float hi) {
    unsigned long long r;
    asm("mov.b64 %0, {%1, %2};" : "=l"(r) : "f"(lo), "f"(hi));
    return r;
}
__device__ __forceinline__ float sum2(unsigned long long p) {
    float lo, hi;
    asm("mov.b64 {%0, %1}, %2;" : "=f"(lo), "=f"(hi) : "l"(p));
    return lo + hi;
}

// ---------------------------------------------------------------------------
// Kernel 1: pq[b][a] = h[b]·Wq[a].  grid(2, B), block(512): 128 blocks
// ---------------------------------------------------------------------------
__global__ void __launch_bounds__(512) k_pq(const float4* __restrict__ h4,
                                            const float4* __restrict__ Wq4) {
    int b = blockIdx.y, half = blockIdx.x, tid = threadIdx.x;
    int lane = tid & 31, warp = tid >> 5;   // 16 warps
    __shared__ float4 sh[RNN / 4];
    if (tid < RNN / 4) sh[tid] = h4[b * (RNN / 4) + tid];
    __syncthreads();
#pragma unroll
    for (int r = 0; r < 4; r++) {
        int a = half * 64 + r * 16 + warp;
        const float4* w = Wq4 + (size_t)a * (RNN / 4);
        float4 wv[8], hv[8];
#pragma unroll
        for (int k = 0; k < 8; k++) wv[k] = w[lane + 32 * k];
#pragma unroll
        for (int k = 0; k < 8; k++) hv[k] = sh[lane + 32 * k];
        float acc = 0.f;
#pragma unroll
        for (int k = 0; k < 8; k++)
            acc += wv[k].x * hv[k].x + wv[k].y * hv[k].y +
                   wv[k].z * hv[k].z + wv[k].w * hv[k].w;
#pragma unroll
        for (int o = 16; o; o >>= 1) acc += __shfl_down_sync(0xffffffffu, acc, o);
        if (lane == 0) g_pq[b * ATT + a] = acc;
    }
}

// ---------------------------------------------------------------------------
// Kernel 2: conv1d + loc projection + tanh energy + softmax partials
// grid(ECH, B), block(128)
// ---------------------------------------------------------------------------
__global__ void __launch_bounds__(128) k_energy(
        const float* __restrict__ pm, const float* __restrict__ aw,
        const float* __restrict__ cw, const float* __restrict__ Wl,
        const float* __restrict__ v,  const unsigned char* __restrict__ mask) {
    int b = blockIdx.y;
    int t0 = blockIdx.x * ETILE;
    int tid = threadIdx.x;
    int lane = tid & 31, warp = tid >> 5;

    __shared__ __align__(16) unsigned long long s_aw2[ETILE + 32];
    __shared__ __align__(16) float s_loc[ETILE * LOC];
    __shared__ float s_pq[ATT], s_v[ATT];
    __shared__ float s_red[ETILE * 4];
    __shared__ float s_w4[4];

    for (int j = tid; j < ETILE + 30; j += 128) {
        int t = t0 - 15 + j;
        float c0 = 0.f, c1 = 0.f;
        if (t >= 0 && t < T) {
            c0 = aw[(size_t)b * 2 * T + t];
            c1 = aw[(size_t)(b * 2 + 1) * T + t];
        }
        s_aw2[j] = pack2(c0, c1);
    }
    if (tid < ATT) { s_pq[tid] = g_pq[b * ATT + tid]; s_v[tid] = v[tid]; }

    int c = tid & 31;
    unsigned long long cw2[KS];
#pragma unroll
    for (int k = 0; k < KS; k++)
        cw2[k] = pack2(cw[c * 62 + k], cw[c * 62 + 31 + k]);
    __syncthreads();

    // conv: fixed channel c per thread, strided tt
    for (int idx = tid; idx < LOC * ETILE; idx += 128) {
        int tt = idx >> 5;
        unsigned long long acc2 = 0ull;
#pragma unroll
        for (int k = 0; k < KS; k++)
            acc2 = fma2(s_aw2[tt + k], cw2[k], acc2);
        s_loc[tt * LOC + c] = sum2(acc2);
    }

    int a = tid;
    unsigned long long wl2[LOC / 2];
#pragma unroll
    for (int j = 0; j < LOC / 2; j++)
        wl2[j] = pack2(Wl[a * LOC + 2 * j], Wl[a * LOC + 2 * j + 1]);
    __syncthreads();
    float pq_a = s_pq[a], v_a = s_v[a];

    const float* pmb = pm + ((size_t)b * T + t0) * ATT + a;
    for (int tt = 0; tt < ETILE; tt += EB) {
        float pmv[EB];
#pragma unroll
        for (int j = 0; j < EB; j++)
            pmv[j] = pmb[(size_t)(tt + j) * ATT];
        float e[EB];
#pragma unroll
        for (int j = 0; j < EB; j++) {
            // loc row via LDS.128 broadcast (ulonglong2 = 16B)
            const ulonglong2* lp = (const ulonglong2*)&s_loc[(tt + j) * LOC];
            unsigned long long a0 = 0ull, a1 = 0ull;
#pragma unroll
            for (int q = 0; q < LOC / 4; q++) {
                ulonglong2 u = lp[q];
                a0 = fma2(u.x, wl2[2 * q], a0);
                a1 = fma2(u.y, wl2[2 * q + 1], a1);
            }
            e[j] = v_a * fast_tanh(pq_a + pmv[j] + sum2(a0) + sum2(a1));
        }
#pragma unroll
        for (int o = 16; o; o >>= 1)
#pragma unroll
            for (int j = 0; j < EB; j++)
                e[j] += __shfl_down_sync(0xffffffffu, e[j], o);
        if (lane == 0)
#pragma unroll
            for (int j = 0; j < EB; j++)
                s_red[(tt + j) * 4 + warp] = e[j];
    }
    __syncthreads();

    float e_t = -INFINITY;
    if (tid < ETILE) {
        e_t = s_red[tid * 4] + s_red[tid * 4 + 1] + s_red[tid * 4 + 2] + s_red[tid * 4 + 3];
        int t = t0 + tid;
        if (mask[b * T + t]) e_t = -INFINITY;
        g_energy[b * T + t] = e_t;
    }
    float m = e_t;
#pragma unroll
    for (int o = 16; o; o >>= 1) m = fmaxf(m, __shfl_xor_sync(0xffffffffu, m, o));
    if (lane == 0) s_w4[warp] = m;
    __syncthreads();
    m = fmaxf(fmaxf(s_w4[0], s_w4[1]), fmaxf(s_w4[2], s_w4[3]));
    float s = (tid < ETILE && m > -INFINITY) ? __expf(e_t - m) : 0.f;
#pragma unroll
    for (int o = 16; o; o >>= 1) s += __shfl_xor_sync(0xffffffffu, s, o);
    __syncthreads();
    if (lane == 0) s_w4[warp] = s;
    __syncthreads();
    if (tid == 0) {
        float2 r; r.x = m; r.y = s_w4[0] + s_w4[1] + s_w4[2] + s_w4[3];
        g_ms[b * ECH + blockIdx.x] = r;
    }
}

// ---------------------------------------------------------------------------
// Kernel 3: softmax combine + weights + context partials + fused reduce
// grid(TCH, B), block(128)
// ---------------------------------------------------------------------------
__global__ void __launch_bounds__(128) k_ctx(const float4* __restrict__ mem,
                                             float* __restrict__ out_w,
                                             float* __restrict__ out_ctx) {
    int b = blockIdx.y, ch = blockIdx.x, tid = threadIdx.x;
    int t0 = ch * CTILE;
    __shared__ float sw[CTILE];
    __shared__ float2 sms[ECH];
    __shared__ float s_m, s_inv;
    __shared__ int s_last;

    if (tid < ECH) sms[tid] = g_ms[b * ECH + tid];
    __syncthreads();
    if (tid == 0) {
        float m = -INFINITY;
#pragma unroll
        for (int j = 0; j < ECH; j++) m = fmaxf(m, sms[j].x);
        float S = 0.f;
#pragma unroll
        for (int j = 0; j < ECH; j++)
            if (sms[j].x > -INFINITY) S += sms[j].y * __expf(sms[j].x - m);
        s_m = m; s_inv = 1.f / S;
    }
    __syncthreads();
    if (tid < CTILE) {
        float e = g_energy[b * T + t0 + tid];
        float wv = __expf(e - s_m) * s_inv;
        sw[tid] = wv;
        out_w[b * T + t0 + tid] = wv;
    }
    __syncthreads();

    const float4* mp = mem + ((size_t)b * T + t0) * (EMB / 4) + tid;
    float ax = 0.f, ay = 0.f, az = 0.f, aww = 0.f;
#pragma unroll 20
    for (int tt = 0; tt < CTILE; tt++) {
        float4 m = __ldcs(mp + (size_t)tt * (EMB / 4));
        float wv = sw[tt];
        ax += wv * m.x; ay += wv * m.y; az += wv * m.z; aww += wv * m.w;
    }
    float4 r; r.x = ax; r.y = ay; r.z = az; r.w = aww;
    ((float4*)g_partial)[(b * TCH + ch) * (EMB / 4) + tid] = r;

    __threadfence();
    if (tid == 0) {
        int cprev = atomicAdd(&g_cnt[b], 1);
        s_last = (cprev == TCH - 1);
    }
    __syncthreads();
    if (s_last) {
        __threadfence();
        const float4* pp = (const float4*)g_partial + (size_t)b * TCH * (EMB / 4) + tid;
        float4 acc = pp[0];
#pragma unroll
        for (int chh = 1; chh < TCH; chh++) {
            float4 p = pp[(size_t)chh * (EMB / 4)];
            acc.x += p.x; acc.y += p.y; acc.z += p.z; acc.w += p.w;
        }
        ((float4*)out_ctx)[b * (EMB / 4) + tid] = acc;
        if (tid == 0) g_cnt[b] = 0;
    }
}

// ---------------------------------------------------------------------------
extern "C" void kernel_launch(void* const* d_in, const int* in_sizes, int n_in,
                              void* d_out, int out_size) {
    const float* h    = (const float*)d_in[0];
    const float* mem  = (const float*)d_in[1];
    const float* pm   = (const float*)d_in[2];
    const float* aw   = (const float*)d_in[3];
    const unsigned char* mask = (const unsigned char*)d_in[4];
    const float* Wq   = (const float*)d_in[5];
    const float* cw   = (const float*)d_in[6];
    const float* Wl   = (const float*)d_in[7];
    const float* v    = (const float*)d_in[8];

    float* out     = (float*)d_out;
    float* out_ctx = out;
    float* out_w   = out + B * EMB;

    dim3 g1(2, B);
    k_pq<<<g1, 512>>>((const float4*)h, (const float4*)Wq);
    dim3 g2(ECH, B);
    k_energy<<<g2, 128>>>(pm, aw, cw, Wl, v, mask);
    dim3 g3(TCH, B);
    k_ctx<<<g3, 128>>>((const float4*)mem, out_w, out_ctx);
}

// round 7
// speedup vs baseline: 1.1442x; 1.1442x over previous
#include <cuda_runtime.h>
#include <math.h>

#define B   64
#define T   1000
#define RNN 1024
#define EMB 512
#define ATT 128
#define LOC 32
#define KS  31
#define ECH 10
#define ETILE 100
#define EB  10
#define NOUT 25    // conv outputs per thread = LOC*ETILE/128
#define TCH 25
#define CTILE 40

__device__ float g_pq[B * ATT];
__device__ float g_energy[B * T];
__device__ float2 g_ms[B * ECH];
__device__ float g_partial[B * TCH * EMB];
__device__ int   g_cnt[B];

__device__ __forceinline__ float fast_tanh(float x) {
    float y;
    asm("tanh.approx.f32 %0, %1;" : "=f"(y) : "f"(x));
    return y;
}
__device__ __forceinline__ unsigned long long fma2(unsigned long long a,
                                                   unsigned long long b,
                                                   unsigned long long c) {
    unsigned long long d;
    asm("fma.rn.f32x2 %0, %1, %2, %3;" : "=l"(d) : "l"(a), "l"(b), "l"(c));
    return d;
}
__device__ __forceinline__ unsigned long long pack2(float lo, float hi) {
    unsigned long long r;
    asm("mov.b64 %0, {%1, %2};" : "=l"(r) : "f"(lo), "f"(hi));
    return r;
}
__device__ __forceinline__ float sum2(unsigned long long p) {
    float lo, hi;
    asm("mov.b64 {%0, %1}, %2;" : "=f"(lo), "=f"(hi) : "l"(p));
    return lo + hi;
}

// ---------------------------------------------------------------------------
// Kernel 1: pq = h @ Wq^T.  grid(8 a-slices, 16 b-groups), block(128)
// Each block: 16 a-rows x 4 b's. Wq row read once, used for 4 b's.
// ---------------------------------------------------------------------------
__global__ void __launch_bounds__(128) k_pq(const float4* __restrict__ h4,
                                            const float4* __restrict__ Wq4) {
    int as = blockIdx.x, bg = blockIdx.y;
    int tid = threadIdx.x, lane = tid & 31, warp = tid >> 5;
    __shared__ float4 sh[4][RNN / 4];

    for (int j = tid; j < 4 * (RNN / 4); j += 128) {
        int bb = j >> 8, i = j & 255;
        sh[bb][i] = h4[(size_t)(bg * 4 + bb) * (RNN / 4) + i];
    }
    __syncthreads();

#pragma unroll
    for (int r = 0; r < 4; r++) {
        int a = as * 16 + warp * 4 + r;
        const float4* w = Wq4 + (size_t)a * (RNN / 4);
        float a0 = 0.f, a1 = 0.f, a2 = 0.f, a3 = 0.f;
#pragma unroll
        for (int k = 0; k < 8; k++) {
            float4 wv = w[lane + 32 * k];
            float4 h0 = sh[0][lane + 32 * k];
            float4 h1 = sh[1][lane + 32 * k];
            float4 h2 = sh[2][lane + 32 * k];
            float4 h3 = sh[3][lane + 32 * k];
            a0 += wv.x * h0.x + wv.y * h0.y + wv.z * h0.z + wv.w * h0.w;
            a1 += wv.x * h1.x + wv.y * h1.y + wv.z * h1.z + wv.w * h1.w;
            a2 += wv.x * h2.x + wv.y * h2.y + wv.z * h2.z + wv.w * h2.w;
            a3 += wv.x * h3.x + wv.y * h3.y + wv.z * h3.z + wv.w * h3.w;
        }
#pragma unroll
        for (int o = 16; o; o >>= 1) {
            a0 += __shfl_down_sync(0xffffffffu, a0, o);
            a1 += __shfl_down_sync(0xffffffffu, a1, o);
            a2 += __shfl_down_sync(0xffffffffu, a2, o);
            a3 += __shfl_down_sync(0xffffffffu, a3, o);
        }
        if (lane == 0) {
            g_pq[(bg * 4 + 0) * ATT + a] = a0;
            g_pq[(bg * 4 + 1) * ATT + a] = a1;
            g_pq[(bg * 4 + 2) * ATT + a] = a2;
            g_pq[(bg * 4 + 3) * ATT + a] = a3;
        }
    }
}

// ---------------------------------------------------------------------------
// Kernel 2: conv1d + loc projection + tanh energy + softmax partials
// grid(ECH, B), block(128). Conv weights in smem; k-outer conv (low regs).
// ---------------------------------------------------------------------------
__global__ void __launch_bounds__(128) k_energy(
        const float* __restrict__ pm, const float* __restrict__ aw,
        const float* __restrict__ cw, const float* __restrict__ Wl,
        const float* __restrict__ v,  const unsigned char* __restrict__ mask) {
    int b = blockIdx.y;
    int t0 = blockIdx.x * ETILE;
    int tid = threadIdx.x;
    int lane = tid & 31, warp = tid >> 5;

    __shared__ __align__(16) unsigned long long s_aw2[ETILE + 32];
    __shared__ __align__(16) unsigned long long s_cw2[LOC * 33]; // [c*33+k]
    __shared__ __align__(16) float s_loc[ETILE * LOC];
    __shared__ float s_pq[ATT], s_v[ATT];
    __shared__ float s_red[ETILE * 4];
    __shared__ float s_w4[4];

    for (int j = tid; j < ETILE + 30; j += 128) {
        int t = t0 - 15 + j;
        float c0 = 0.f, c1 = 0.f;
        if (t >= 0 && t < T) {
            c0 = aw[(size_t)b * 2 * T + t];
            c1 = aw[(size_t)(b * 2 + 1) * T + t];
        }
        s_aw2[j] = pack2(c0, c1);
    }
    for (int j = tid; j < LOC * KS; j += 128) {
        int c = j / KS, k = j - c * KS;
        s_cw2[c * 33 + k] = pack2(cw[c * 62 + k], cw[c * 62 + 31 + k]);
    }
    if (tid < ATT) { s_pq[tid] = g_pq[b * ATT + tid]; s_v[tid] = v[tid]; }
    __syncthreads();

    // conv, k-outer: thread owns channel c=lane, 25 t-outputs tt = wtt+4j
    {
        int c = lane, wtt = warp;
        unsigned long long acc2[NOUT];
#pragma unroll
        for (int j = 0; j < NOUT; j++) acc2[j] = 0ull;
        for (int k = 0; k < KS; k++) {
            unsigned long long cwk = s_cw2[c * 33 + k];
#pragma unroll
            for (int j = 0; j < NOUT; j++)
                acc2[j] = fma2(s_aw2[wtt + 4 * j + k], cwk, acc2[j]);
        }
#pragma unroll
        for (int j = 0; j < NOUT; j++)
            s_loc[(wtt + 4 * j) * LOC + c] = sum2(acc2[j]);
    }

    int a = tid;
    unsigned long long wl2[LOC / 2];
#pragma unroll
    for (int j = 0; j < LOC / 2; j++)
        wl2[j] = pack2(Wl[a * LOC + 2 * j], Wl[a * LOC + 2 * j + 1]);
    __syncthreads();
    float pq_a = s_pq[a], v_a = s_v[a];

    const float* pmb = pm + ((size_t)b * T + t0) * ATT + a;
    for (int tt = 0; tt < ETILE; tt += EB) {
        float pmv[EB];
#pragma unroll
        for (int j = 0; j < EB; j++)
            pmv[j] = pmb[(size_t)(tt + j) * ATT];
        float e[EB];
#pragma unroll
        for (int j = 0; j < EB; j++) {
            const ulonglong2* lp = (const ulonglong2*)&s_loc[(tt + j) * LOC];
            unsigned long long a0 = 0ull, a1 = 0ull;
#pragma unroll
            for (int q = 0; q < LOC / 4; q++) {
                ulonglong2 u = lp[q];
                a0 = fma2(u.x, wl2[2 * q], a0);
                a1 = fma2(u.y, wl2[2 * q + 1], a1);
            }
            e[j] = v_a * fast_tanh(pq_a + pmv[j] + sum2(a0) + sum2(a1));
        }
#pragma unroll
        for (int o = 16; o; o >>= 1)
#pragma unroll
            for (int j = 0; j < EB; j++)
                e[j] += __shfl_down_sync(0xffffffffu, e[j], o);
        if (lane == 0)
#pragma unroll
            for (int j = 0; j < EB; j++)
                s_red[(tt + j) * 4 + warp] = e[j];
    }
    __syncthreads();

    float e_t = -INFINITY;
    if (tid < ETILE) {
        e_t = s_red[tid * 4] + s_red[tid * 4 + 1] + s_red[tid * 4 + 2] + s_red[tid * 4 + 3];
        int t = t0 + tid;
        if (mask[b * T + t]) e_t = -INFINITY;
        g_energy[b * T + t] = e_t;
    }
    float m = e_t;
#pragma unroll
    for (int o = 16; o; o >>= 1) m = fmaxf(m, __shfl_xor_sync(0xffffffffu, m, o));
    if (lane == 0) s_w4[warp] = m;
    __syncthreads();
    m = fmaxf(fmaxf(s_w4[0], s_w4[1]), fmaxf(s_w4[2], s_w4[3]));
    float s = (tid < ETILE && m > -INFINITY) ? __expf(e_t - m) : 0.f;
#pragma unroll
    for (int o = 16; o; o >>= 1) s += __shfl_xor_sync(0xffffffffu, s, o);
    __syncthreads();
    if (lane == 0) s_w4[warp] = s;
    __syncthreads();
    if (tid == 0) {
        float2 r; r.x = m; r.y = s_w4[0] + s_w4[1] + s_w4[2] + s_w4[3];
        g_ms[b * ECH + blockIdx.x] = r;
    }
}

// ---------------------------------------------------------------------------
// Kernel 3: softmax combine + weights + context partials + fused reduce
// grid(TCH, B), block(128)
// ---------------------------------------------------------------------------
__global__ void __launch_bounds__(128) k_ctx(const float4* __restrict__ mem,
                                             float* __restrict__ out_w,
                                             float* __restrict__ out_ctx) {
    int b = blockIdx.y, ch = blockIdx.x, tid = threadIdx.x;
    int t0 = ch * CTILE;
    __shared__ float sw[CTILE];
    __shared__ float2 sms[ECH];
    __shared__ float s_m, s_inv;
    __shared__ int s_last;

    if (tid < ECH) sms[tid] = g_ms[b * ECH + tid];
    __syncthreads();
    if (tid == 0) {
        float m = -INFINITY;
#pragma unroll
        for (int j = 0; j < ECH; j++) m = fmaxf(m, sms[j].x);
        float S = 0.f;
#pragma unroll
        for (int j = 0; j < ECH; j++)
            if (sms[j].x > -INFINITY) S += sms[j].y * __expf(sms[j].x - m);
        s_m = m; s_inv = 1.f / S;
    }
    __syncthreads();
    if (tid < CTILE) {
        float e = g_energy[b * T + t0 + tid];
        float wv = __expf(e - s_m) * s_inv;
        sw[tid] = wv;
        out_w[b * T + t0 + tid] = wv;
    }
    __syncthreads();

    const float4* mp = mem + ((size_t)b * T + t0) * (EMB / 4) + tid;
    float ax = 0.f, ay = 0.f, az = 0.f, aww = 0.f;
#pragma unroll 20
    for (int tt = 0; tt < CTILE; tt++) {
        float4 m = __ldcs(mp + (size_t)tt * (EMB / 4));
        float wv = sw[tt];
        ax += wv * m.x; ay += wv * m.y; az += wv * m.z; aww += wv * m.w;
    }
    float4 r; r.x = ax; r.y = ay; r.z = az; r.w = aww;
    ((float4*)g_partial)[(b * TCH + ch) * (EMB / 4) + tid] = r;

    __threadfence();
    if (tid == 0) {
        int cprev = atomicAdd(&g_cnt[b], 1);
        s_last = (cprev == TCH - 1);
    }
    __syncthreads();
    if (s_last) {
        __threadfence();
        const float4* pp = (const float4*)g_partial + (size_t)b * TCH * (EMB / 4) + tid;
        float4 acc = pp[0];
#pragma unroll
        for (int chh = 1; chh < TCH; chh++) {
            float4 p = pp[(size_t)chh * (EMB / 4)];
            acc.x += p.x; acc.y += p.y; acc.z += p.z; acc.w += p.w;
        }
        ((float4*)out_ctx)[b * (EMB / 4) + tid] = acc;
        if (tid == 0) g_cnt[b] = 0;
    }
}

// ---------------------------------------------------------------------------
extern "C" void kernel_launch(void* const* d_in, const int* in_sizes, int n_in,
                              void* d_out, int out_size) {
    const float* h    = (const float*)d_in[0];
    const float* mem  = (const float*)d_in[1];
    const float* pm   = (const float*)d_in[2];
    const float* aw   = (const float*)d_in[3];
    const unsigned char* mask = (const unsigned char*)d_in[4];
    const float* Wq   = (const float*)d_in[5];
    const float* cw   = (const float*)d_in[6];
    const float* Wl   = (const float*)d_in[7];
    const float* v    = (const float*)d_in[8];

    float* out     = (float*)d_out;
    float* out_ctx = out;
    float* out_w   = out + B * EMB;

    dim3 g1(8, 16);
    k_pq<<<g1, 128>>>((const float4*)h, (const float4*)Wq);
    dim3 g2(ECH, B);
    k_energy<<<g2, 128>>>(pm, aw, cw, Wl, v, mask);
    dim3 g3(TCH, B);
    k_ctx<<<g3, 128>>>((const float4*)mem, out_w, out_ctx);
}